// round 9
// baseline (speedup 1.0000x reference)
#include <cuda_runtime.h>
#include <math.h>

#define N_TOT 4096
#define C_DIM 256
#define K_NEG 128
#define HW 1024
#define INV_T (1.0f / 0.07f)
#define Q8 256.0f
#define NEG_SCALE (INV_T / (Q8 * Q8))
#define NEG_INF (-1e30f)
#define FIX_SCALE 4294967296.0

#define NTILE 128                 // positions per gather CTA
#define ITILE 256                 // k-rows per idx tile
#define NBUCK (N_TOT / ITILE)     // 16 idx tiles
#define SMEM3 ((ITILE + NTILE) * C_DIM)   // 96 KB dynamic smem

// Scratch (allocation-free rule: __device__ globals)
__device__ __align__(16) signed char g_qn8[N_TOT * C_DIM]; // q int8*256
__device__ __align__(16) signed char g_kn8[N_TOT * C_DIM]; // k int8*256
__device__ float    g_lpos[N_TOT];                         // l_pos logit (fp32)
__device__ unsigned g_sneg[N_TOT * K_NEG];                 // bucketed: m | (idx&255)<<7
__device__ int      g_seg[N_TOT * (NBUCK + 1)];            // per-row bucket offsets
__device__ float    g_lneg[N_TOT * K_NEG];                 // negative logits
__device__ unsigned long long g_acc;                       // fixed-point loss sum
__device__ unsigned g_done;                                // block completion ctr

__device__ __forceinline__ signed char q8(float v) {
    int iv = __float2int_rn(v * Q8);
    iv = max(-127, min(127, iv));
    return (signed char)iv;
}

// ---------------------------------------------------------------------------
// K1: normalize q,k over C, transpose [B,C,HW] -> [N,C] int8, fp32 l_pos.
// grid = 512 tiles of 8 positions, block (8,32).  (known-good from R5/R6)
// ---------------------------------------------------------------------------
__global__ void __launch_bounds__(256) norm_transpose_kernel(
    const float* __restrict__ fq, const float* __restrict__ fk)
{
    if (blockIdx.x == 0 && threadIdx.x == 0 && threadIdx.y == 0)
        g_acc = 0ull;

    const int n0  = blockIdx.x * 8;
    const int b   = n0 / HW;
    const int hw0 = n0 % HW;
    const int tx  = threadIdx.x;          // 0..7
    const int ty  = threadIdx.y;          // 0..31

    __shared__ float tq[C_DIM][9];
    __shared__ float tk[C_DIM][9];
    __shared__ float ssq[32][8], ssk[32][8], sdt[32][8];
    __shared__ float sinvq[8], sinvk[8];

    const size_t boff = (size_t)b * C_DIM * HW + hw0 + tx;
    const float* bq = fq + boff;
    const float* bk = fk + boff;

    float aq = 0.f, ak = 0.f, ad = 0.f;
    #pragma unroll
    for (int cc = 0; cc < 8; cc++) {
        int c = cc * 32 + ty;
        float vq = bq[(size_t)c * HW];
        float vk = bk[(size_t)c * HW];
        tq[c][tx] = vq;
        tk[c][tx] = vk;
        aq += vq * vq;
        ak += vk * vk;
        ad += vq * vk;
    }
    ssq[ty][tx] = aq;
    ssk[ty][tx] = ak;
    sdt[ty][tx] = ad;
    __syncthreads();

    if (ty == 0) {
        float sq = 0.f, sk = 0.f, sd = 0.f;
        #pragma unroll
        for (int r = 0; r < 32; r++) {
            sq += ssq[r][tx];
            sk += ssk[r][tx];
            sd += sdt[r][tx];
        }
        float iq = rsqrtf(fmaxf(sq, 1e-24f));
        float ik = rsqrtf(fmaxf(sk, 1e-24f));
        sinvq[tx] = iq;
        sinvk[tx] = ik;
        g_lpos[n0 + tx] = sd * iq * ik * INV_T;
    }
    __syncthreads();

    const int c = ty * 8 + tx;
    #pragma unroll
    for (int r = 0; r < 8; r++) {
        size_t o = (size_t)(n0 + r) * C_DIM + c;
        g_qn8[o] = q8(tq[c][r] * sinvq[r]);
        g_kn8[o] = q8(tk[c][r] * sinvk[r]);
    }
}

// ---------------------------------------------------------------------------
// K2: bucket each row's 128 shifted indices into 16 idx-tiles.
// One warp per position n; grid 1024 x block 128.
// ---------------------------------------------------------------------------
__global__ void __launch_bounds__(128) bucket_kernel(const int* __restrict__ negs)
{
    const int warp = threadIdx.x >> 5;
    const int lane = threadIdx.x & 31;
    const int n    = blockIdx.x * 4 + warp;

    __shared__ int hist[4][NBUCK];
    __shared__ int cur[4][NBUCK];

    if (lane < NBUCK) hist[warp][lane] = 0;
    __syncwarp();

    int idxv[4], bv[4];
    #pragma unroll
    for (int j = 0; j < 4; j++) {
        int m  = lane + j * 32;
        int ix = negs[n * K_NEG + m];
        ix += (ix >= n) ? 1 : 0;          // self-exclusion shift
        idxv[j] = ix;
        bv[j]   = ix >> 8;                // idx tile (256 rows each)
        atomicAdd(&hist[warp][bv[j]], 1);
    }
    __syncwarp();

    if (lane < NBUCK) {
        int pre = 0;
        #pragma unroll
        for (int t = 0; t < NBUCK; t++)
            if (t < lane) pre += hist[warp][t];
        cur[warp][lane] = pre;
        g_seg[n * (NBUCK + 1) + lane] = pre;
        if (lane == NBUCK - 1)
            g_seg[n * (NBUCK + 1) + NBUCK] = pre + hist[warp][lane];
    }
    __syncwarp();

    #pragma unroll
    for (int j = 0; j < 4; j++) {
        int m    = lane + j * 32;
        int slot = atomicAdd(&cur[warp][bv[j]], 1);
        g_sneg[n * K_NEG + slot] =
            (unsigned)m | ((unsigned)(idxv[j] & (ITILE - 1)) << 7);
    }
}

// ---------------------------------------------------------------------------
// K3: tiled gather-dot. CTA = (n-tile of 128 positions) x (idx-tile of 256
// k-rows). Loads both tiles to smem coalesced, then serves ~1024 entries as
// conflict-free smem row reads (warp-LDS.64 spans all 32 banks) + dp4a +
// native full-warp REDUX. grid = (32, 16), block 256, 96KB dynamic smem.
// ---------------------------------------------------------------------------
extern __shared__ signed char smem3[];

__global__ void __launch_bounds__(256) gather_dot_kernel()
{
    signed char* sk = smem3;                       // 64 KB: k idx-tile
    signed char* sq = smem3 + ITILE * C_DIM;       // 32 KB: q n-tile
    const int ntile = blockIdx.x;                  // 0..31
    const int it    = blockIdx.y;                  // 0..15
    const int tid   = threadIdx.x;
    const int lane  = tid & 31;
    const int warp  = tid >> 5;

    // coalesced tile loads (uint4)
    {
        const uint4* gk = (const uint4*)(g_kn8 + (size_t)it * ITILE * C_DIM);
        uint4* sk4 = (uint4*)sk;
        #pragma unroll
        for (int i = 0; i < 16; i++) sk4[tid + i * 256] = gk[tid + i * 256];
        const uint4* gq = (const uint4*)(g_qn8 + (size_t)ntile * NTILE * C_DIM);
        uint4* sq4 = (uint4*)sq;
        #pragma unroll
        for (int i = 0; i < 8; i++) sq4[tid + i * 256] = gq[tid + i * 256];
    }
    __syncthreads();

    // 8 warps x 16 positions each
    #pragma unroll 1
    for (int p = 0; p < 16; p++) {
        const int nl = warp * 16 + p;
        const int n  = ntile * NTILE + nl;
        const uint2 qv = ((const uint2*)(sq + nl * C_DIM))[lane];
        const int s = g_seg[n * (NBUCK + 1) + it];
        const int e = g_seg[n * (NBUCK + 1) + it + 1];

        for (int base = s; base < e; base += 32) {
            const int cnt = min(32, e - base);
            unsigned pk = 0;
            if (lane < cnt) pk = g_sneg[n * K_NEG + base + lane];
            for (int j = 0; j < cnt; j++) {
                const unsigned pe = __shfl_sync(0xffffffffu, pk, j);
                const int m  = pe & 127;
                const int il = (pe >> 7) & 255;
                const uint2 kv = ((const uint2*)(sk + il * C_DIM))[lane];
                int d = __dp4a((int)kv.x, (int)qv.x, 0);
                d     = __dp4a((int)kv.y, (int)qv.y, d);
                d = __reduce_add_sync(0xffffffffu, d);   // native 32-lane REDUX
                if (lane == 0)
                    g_lneg[n * K_NEG + m] = (float)d * NEG_SCALE;
            }
        }
    }
}

// ---------------------------------------------------------------------------
// K4: per-row logsumexp over [l_pos, 128 negs] + fused deterministic mean.
// ---------------------------------------------------------------------------
__global__ void __launch_bounds__(128) lse_kernel(float* __restrict__ out)
{
    const int n    = blockIdx.x;
    const int tid  = threadIdx.x;
    const int lane = tid & 31;
    const int warp = tid >> 5;
    __shared__ float red[4];

    const float x     = (tid == 0) ? g_lpos[n] : g_lneg[n * K_NEG + tid - 1];
    const float extra = (tid == 0) ? g_lneg[n * K_NEG + 127] : NEG_INF;

    float mx = fmaxf(x, extra);
    #pragma unroll
    for (int o = 16; o > 0; o >>= 1)
        mx = fmaxf(mx, __shfl_xor_sync(0xffffffffu, mx, o));
    if (lane == 0) red[warp] = mx;
    __syncthreads();
    mx = fmaxf(fmaxf(red[0], red[1]), fmaxf(red[2], red[3]));
    __syncthreads();

    float e = expf(x - mx) + ((tid == 0) ? expf(extra - mx) : 0.f);
    #pragma unroll
    for (int o = 16; o > 0; o >>= 1) e += __shfl_xor_sync(0xffffffffu, e, o);
    if (lane == 0) red[warp] = e;
    __syncthreads();

    if (tid == 0) {
        float s = red[0] + red[1] + red[2] + red[3];
        float rowloss = mx + logf(s) - x;         // x == l_pos on tid 0
        unsigned long long fx =
            (unsigned long long)llrintf(rowloss * (float)FIX_SCALE);
        atomicAdd(&g_acc, fx);
        __threadfence();
        unsigned t = atomicAdd(&g_done, 1u);
        if (t == (unsigned)(gridDim.x - 1)) {
            unsigned long long total = atomicAdd(&g_acc, 0ull);
            out[0] = (float)((double)total * (1.0 / FIX_SCALE) * (1.0 / N_TOT));
            g_done = 0u;
        }
    }
}

// ---------------------------------------------------------------------------
extern "C" void kernel_launch(void* const* d_in, const int* in_sizes, int n_in,
                              void* d_out, int out_size)
{
    const float* fq   = (const float*)d_in[0];
    const float* fk   = (const float*)d_in[1];
    const int*   negs = (const int*)d_in[2];
    float*       out  = (float*)d_out;

    // idempotent attribute set for 96KB dynamic smem (host-side, not a stream op)
    cudaFuncSetAttribute(gather_dot_kernel,
                         cudaFuncAttributeMaxDynamicSharedMemorySize, SMEM3);

    norm_transpose_kernel<<<512, dim3(8, 32)>>>(fq, fk);
    bucket_kernel<<<N_TOT / 4, 128>>>(negs);
    gather_dot_kernel<<<dim3(N_TOT / NTILE, NBUCK), 256, SMEM3>>>();
    lse_kernel<<<N_TOT, 128>>>(out);
}

// round 10
// speedup vs baseline: 2.4880x; 2.4880x over previous
#include <cuda_runtime.h>
#include <math.h>

#define N_TOT 4096
#define C_DIM 256
#define K_NEG 128
#define HW 1024
#define INV_T (1.0f / 0.07f)
#define Q8 256.0f                        // int8 quant scale for both q and k
#define NEG_SCALE (INV_T / (Q8 * Q8))    // logit scale for int dots
#define NEG_INF (-1e30f)
#define FIX_SCALE 4294967296.0           // 2^32

// Scratch (allocation-free rule: __device__ globals)
__device__ __align__(16) signed char g_qn8[N_TOT * C_DIM]; // q int8*256
__device__ __align__(16) signed char g_kn8[N_TOT * C_DIM]; // k int8*256
__device__ float g_lpos[N_TOT];                             // l_pos logit (fp32)
__device__ unsigned long long g_acc;                        // fixed-point loss sum
__device__ unsigned int       g_done;                       // block completion ctr

__device__ __forceinline__ signed char q8(float v) {
    int iv = __float2int_rn(v * Q8);
    iv = max(-127, min(127, iv));
    return (signed char)iv;
}

// ---------------------------------------------------------------------------
// K1: normalize q,k over C, transpose [B,C,HW] -> [N,C] int8, fp32 l_pos.
// grid = 512 tiles of 8 positions, block (8,32).
// ---------------------------------------------------------------------------
__global__ void __launch_bounds__(256) norm_transpose_kernel(
    const float* __restrict__ fq, const float* __restrict__ fk)
{
    if (blockIdx.x == 0 && threadIdx.x == 0 && threadIdx.y == 0)
        g_acc = 0ull;

    const int n0  = blockIdx.x * 8;       // 8 | 1024, tile never crosses batch
    const int b   = n0 / HW;
    const int hw0 = n0 % HW;
    const int tx  = threadIdx.x;          // 0..7  : hw within tile
    const int ty  = threadIdx.y;          // 0..31 : channel group

    __shared__ float tq[C_DIM][9];
    __shared__ float tk[C_DIM][9];
    __shared__ float ssq[32][8], ssk[32][8], sdt[32][8];
    __shared__ float sinvq[8], sinvk[8];

    const size_t boff = (size_t)b * C_DIM * HW + hw0 + tx;
    const float* bq = fq + boff;
    const float* bk = fk + boff;

    float aq = 0.f, ak = 0.f, ad = 0.f;
    #pragma unroll
    for (int cc = 0; cc < 8; cc++) {      // 16 loads in flight per thread
        int c = cc * 32 + ty;
        float vq = bq[(size_t)c * HW];
        float vk = bk[(size_t)c * HW];
        tq[c][tx] = vq;
        tk[c][tx] = vk;
        aq += vq * vq;
        ak += vk * vk;
        ad += vq * vk;
    }
    ssq[ty][tx] = aq;
    ssk[ty][tx] = ak;
    sdt[ty][tx] = ad;
    __syncthreads();

    if (ty == 0) {
        float sq = 0.f, sk = 0.f, sd = 0.f;
        #pragma unroll
        for (int r = 0; r < 32; r++) {
            sq += ssq[r][tx];
            sk += ssk[r][tx];
            sd += sdt[r][tx];
        }
        float iq = rsqrtf(fmaxf(sq, 1e-24f));   // 1/max(||q||,1e-12)
        float ik = rsqrtf(fmaxf(sk, 1e-24f));
        sinvq[tx] = iq;
        sinvk[tx] = ik;
        g_lpos[n0 + tx] = sd * iq * ik * INV_T; // fp32 positive logit
    }
    __syncthreads();

    const int c = ty * 8 + tx;            // thread owns one channel
    #pragma unroll
    for (int r = 0; r < 8; r++) {
        size_t o = (size_t)(n0 + r) * C_DIM + c;
        g_qn8[o] = q8(tq[c][r] * sinvq[r]);
        g_kn8[o] = q8(tk[c][r] * sinvk[r]);
    }
}

// ---------------------------------------------------------------------------
// K2: per-row gather-dot with an 8-deep rotating prefetch pipeline.
// One block (128 thr) per position n. Warp handles 32 negatives, one row per
// warp-LDG: lane reads uint2 (8B) -> 256B fully coalesced (2 lines). kv[8]
// keeps 8 independent LDGs in flight per warp; the prefetch is issued BEFORE
// the REDUX of the current row so reductions never fence pending loads.
// ---------------------------------------------------------------------------
__global__ void __launch_bounds__(128) patchnce_main_kernel(
    const int* __restrict__ negs, float* __restrict__ out)
{
    const int n    = blockIdx.x;
    const int tid  = threadIdx.x;
    const int lane = tid & 31;
    const int warp = tid >> 5;

    __shared__ float slog[132];           // 129 logits (0 = l_pos)
    __shared__ float red[4];

    const uint2* __restrict__ kb = (const uint2*)g_kn8;

    // this lane's 8 q channels, int8 (direct gmem load, no staging)
    const uint2 qv = __ldg((const uint2*)(g_qn8 + (size_t)n * C_DIM) + lane);
    if (tid == 0) slog[0] = g_lpos[n];

    // per-lane negative index (lane l of warp w owns broadcast slot l)
    int myidx = negs[(size_t)n * K_NEG + warp * 32 + lane];
    myidx += (myidx >= n) ? 1 : 0;        // self-exclusion shift

    // prologue: fill the 8-deep pipeline
    uint2 kv[8];
    #pragma unroll
    for (int j = 0; j < 8; j++) {
        const int ix = __shfl_sync(0xffffffffu, myidx, j);
        kv[j] = __ldg(kb + (size_t)ix * 32 + lane);
    }

    #pragma unroll
    for (int j = 0; j < 32; j++) {
        const uint2 v = kv[j & 7];        // consume (copy before refill)
        if (j < 24) {                     // refill slot before any reduction
            const int ix = __shfl_sync(0xffffffffu, myidx, j + 8);
            kv[j & 7] = __ldg(kb + (size_t)ix * 32 + lane);
        }
        int d = __dp4a((int)v.x, (int)qv.x, 0);
        d     = __dp4a((int)v.y, (int)qv.y, d);
        d = __reduce_add_sync(0xffffffffu, d);    // native 32-lane REDUX
        if (lane == 0)
            slog[1 + warp * 32 + j] = (float)d * NEG_SCALE;
    }
    __syncthreads();

    // logsumexp over 129 logits (thread 0 also covers slog[128])
    const float x     = slog[tid];
    const float extra = (tid == 0) ? slog[128] : NEG_INF;

    float mx = fmaxf(x, extra);
    #pragma unroll
    for (int o = 16; o > 0; o >>= 1)
        mx = fmaxf(mx, __shfl_xor_sync(0xffffffffu, mx, o));
    if (lane == 0) red[warp] = mx;
    __syncthreads();
    mx = fmaxf(fmaxf(red[0], red[1]), fmaxf(red[2], red[3]));
    __syncthreads();                      // WAR on red[]

    float e = expf(x - mx) + ((tid == 0) ? expf(extra - mx) : 0.f);
    #pragma unroll
    for (int o = 16; o > 0; o >>= 1) e += __shfl_xor_sync(0xffffffffu, e, o);
    if (lane == 0) red[warp] = e;
    __syncthreads();

    if (tid == 0) {
        float s = red[0] + red[1] + red[2] + red[3];
        float rowloss = mx + logf(s) - slog[0];   // >= 0 always
        unsigned long long fx =
            (unsigned long long)llrintf(rowloss * (float)FIX_SCALE);
        atomicAdd(&g_acc, fx);            // integer atomics commute: deterministic
        __threadfence();
        unsigned int t = atomicAdd(&g_done, 1u);
        if (t == (unsigned int)(gridDim.x - 1)) {
            unsigned long long total = atomicAdd(&g_acc, 0ull);
            out[0] = (float)((double)total * (1.0 / FIX_SCALE) * (1.0 / N_TOT));
            g_done = 0u;                  // reset for next graph replay
        }
    }
}

// ---------------------------------------------------------------------------
extern "C" void kernel_launch(void* const* d_in, const int* in_sizes, int n_in,
                              void* d_out, int out_size)
{
    const float* fq   = (const float*)d_in[0];
    const float* fk   = (const float*)d_in[1];
    const int*   negs = (const int*)d_in[2];
    float*       out  = (float*)d_out;

    norm_transpose_kernel<<<512, dim3(8, 32)>>>(fq, fk);
    patchnce_main_kernel<<<N_TOT, 128>>>(negs, out);
}